// round 6
// baseline (speedup 1.0000x reference)
#include <cuda_runtime.h>
#include <math.h>
#include <stdint.h>

#define SLOPE 0.01f
constexpr float RCOEF = 1.0f - SLOPE;

// -------- problem constants --------
constexpr int Dd    = 32;
constexpr int Hh    = 128;
constexpr int Bb    = 64;
constexpr int Tt    = 514;
constexpr int TTt   = 512;
constexpr int NTOT  = Bb * TTt;          // 32768
constexpr int NTILE = 128;
constexpr int NTILES = NTOT / NTILE;     // 256

// output layout (reference return order, concatenated)
constexpr size_t RES_OFF  = 0;                        // (64,512,32)
constexpr size_t SUM_OFF  = (size_t)Bb * TTt * Dd;    // (64,)
constexpr size_t HIST_OFF = SUM_OFF + Bb;             // (32,32768,1,64)

// -------- shared offsets (u32 units) --------
constexpr int XWS = 36;                  // x-window row stride
constexpr int W1S = 68;                  // W1 row stride
constexpr int O_XH    = 0;                               // 130*36
constexpr int O_XL    = O_XH + 130 * XWS;                // 4680
constexpr int O_W1H   = O_XL + 130 * XWS;                // 9360
constexpr int O_W1L   = O_W1H + Hh * W1S;                // 18064
constexpr int O_MASK  = O_W1L + Hh * W1S;                // 26768
constexpr int O_S     = O_MASK + 512;                    // 27280
constexpr int O_WLAST = O_S + 64;                        // 27344
constexpr int O_B1    = O_WLAST + 128;                   // 27472
constexpr int O_W2    = O_B1 + 128;                      // 27600
constexpr int O_W2H   = O_W2 + 128;                      // 27728
constexpr int O_W2L   = O_W2H + 128;                     // 27856
constexpr int O_YY    = O_W2L + 128;                     // 27984 (132)
constexpr int O_RS    = O_YY + 132;                      // 28116
constexpr int O_JS    = O_RS + 128;                      // 28244
constexpr int O_RED   = O_JS + 128;                      // 28372
constexpr int SMEM_U32 = O_RED + 4;                      // 28376
constexpr int SMEM_BYTES = SMEM_U32 * 4;                 // 113504

__device__ __forceinline__ uint32_t f2tf32(float f) {
    uint32_t u;
    asm("cvt.rna.tf32.f32 %0, %1;" : "=r"(u) : "f"(f));
    return u;
}
__device__ __forceinline__ void split_tf32(float v, uint32_t& hi, uint32_t& lo) {
    hi = f2tf32(v);
    lo = f2tf32(v - __uint_as_float(hi));
}

__device__ __forceinline__ void mma8(float* d, const uint32_t* a, uint32_t b0, uint32_t b1) {
    asm volatile(
        "mma.sync.aligned.m16n8k8.row.col.f32.tf32.tf32.f32 "
        "{%0,%1,%2,%3}, {%4,%5,%6,%7}, {%8,%9}, {%0,%1,%2,%3};"
        : "+f"(d[0]), "+f"(d[1]), "+f"(d[2]), "+f"(d[3])
        : "r"(a[0]), "r"(a[1]), "r"(a[2]), "r"(a[3]), "r"(b0), "r"(b1));
}

__global__ void zero_sum_kernel(float* out) { out[SUM_OFF + threadIdx.x] = 0.0f; }

extern __shared__ uint32_t smemu[];

__global__ __launch_bounds__(256, 2)
void fused_mma(const float* __restrict__ x,  const float* __restrict__ W1,
               const float* __restrict__ b1, const float* __restrict__ W2,
               const float* __restrict__ b2, float* __restrict__ out)
{
    float* sf = (float*)smemu;
    const int tid  = threadIdx.x;
    const int lane = tid & 31;
    const int w    = tid >> 5;
    const int lr   = lane >> 2;   // 0..7
    const int lc   = lane & 3;    // 0..3

    const int d  = blockIdx.x;
    const int n0 = blockIdx.y * NTILE;
    const int bb = n0 / TTt;
    const int t0 = n0 % TTt;

    // ---------------- preamble: stage hi/lo tiles ----------------
    {
        const float* W1g = W1 + (size_t)d * Hh * 65;
        for (int idx = tid; idx < Hh * 65; idx += 256) {
            int h = idx / 65;
            int k = idx - h * 65;
            float v = W1g[idx];
            if (k == 64) sf[O_WLAST + h] = v;
            else {
                uint32_t hi, lo;
                split_tf32(v, hi, lo);
                smemu[O_W1H + h * W1S + k] = hi;
                smemu[O_W1L + h * W1S + k] = lo;
            }
        }
        const float* xg = x + ((size_t)bb * Tt + t0) * Dd;
        for (int idx = tid; idx < 130 * 32; idx += 256) {
            int r = idx >> 5, c = idx & 31;
            float v = xg[idx];
            uint32_t hi, lo;
            split_tf32(v, hi, lo);
            smemu[O_XH + r * XWS + c] = hi;
            smemu[O_XL + r * XWS + c] = lo;
            if (c == d) sf[O_YY + r] = v;
        }
        if (tid < 128) {
            float w2v = W2[(size_t)d * Hh + tid];
            sf[O_B1 + tid] = b1[(size_t)d * Hh + tid];
            sf[O_W2 + tid] = w2v;
            uint32_t hi, lo;
            split_tf32(w2v, hi, lo);
            smemu[O_W2H + tid] = hi;
            smemu[O_W2L + tid] = lo;
            sf[O_RS + tid] = 0.0f;
            sf[O_JS + tid] = 0.0f;
        }
        if (tid == 0) sf[O_RED] = 0.0f;
    }
    __syncthreads();

    // colsums S[k] = sum_h w2[h]*W1[h][k]  (W1 reconstructed from hi+lo; read after next barrier)
    if (tid < 64) {
        float s = 0.0f;
        #pragma unroll 8
        for (int h = 0; h < Hh; h++) {
            float v = __uint_as_float(smemu[O_W1H + h * W1S + tid]) +
                      __uint_as_float(smemu[O_W1L + h * W1S + tid]);
            s = fmaf(sf[O_W2 + h], v, s);
        }
        sf[O_S + tid] = s;
    }

    // ---------------- GEMM A: pre[128n x 128h] = XX @ W1[:, :64]^T (3xTF32) ----------------
    const int nblk = (w & 3) * 32;
    const int hblk = (w >> 2) * 64;

    float acc[2][8][4];
    #pragma unroll
    for (int i = 0; i < 2; i++)
        #pragma unroll
        for (int j = 0; j < 8; j++)
            #pragma unroll
            for (int q = 0; q < 4; q++) acc[i][j][q] = 0.0f;

    #pragma unroll 2
    for (int s = 0; s < 8; s++) {
        const int l  = s >> 2;
        const int c0 = ((8 * s) & 31) + lc;
        uint32_t ah[2][4], al[2][4];
        #pragma unroll
        for (int i = 0; i < 2; i++) {
            int base = (nblk + 16 * i + lr + l) * XWS + c0;
            ah[i][0] = smemu[O_XH + base];
            ah[i][1] = smemu[O_XH + base + 8 * XWS];
            ah[i][2] = smemu[O_XH + base + 4];
            ah[i][3] = smemu[O_XH + base + 8 * XWS + 4];
            al[i][0] = smemu[O_XL + base];
            al[i][1] = smemu[O_XL + base + 8 * XWS];
            al[i][2] = smemu[O_XL + base + 4];
            al[i][3] = smemu[O_XL + base + 8 * XWS + 4];
        }
        #pragma unroll
        for (int j = 0; j < 8; j++) {
            int hb = (hblk + 8 * j + lr) * W1S + 8 * s + lc;
            uint32_t bh0 = smemu[O_W1H + hb], bh1 = smemu[O_W1H + hb + 4];
            uint32_t bl0 = smemu[O_W1L + hb], bl1 = smemu[O_W1L + hb + 4];
            #pragma unroll
            for (int i = 0; i < 2; i++) {
                mma8(acc[i][j], ah[i], bh0, bh1);
                mma8(acc[i][j], ah[i], bl0, bl1);
                mma8(acc[i][j], al[i], bh0, bh1);
            }
        }
    }

    // ---------------- epilogue A: mask bits, residual + jac[:,64] partials ----------------
    {
        #pragma unroll
        for (int i = 0; i < 2; i++) {
            #pragma unroll
            for (int ci = 0; ci < 2; ci++) {
                const int row = nblk + 16 * i + 8 * ci + lr;
                const float yyv = sf[O_YY + row + 2];
                float rp = 0.0f, jp = 0.0f;
                uint32_t m0 = 0, m1 = 0;
                #pragma unroll
                for (int j = 0; j < 8; j++) {
                    #pragma unroll
                    for (int cj = 0; cj < 2; cj++) {
                        const int h = hblk + 8 * j + 2 * lc + cj;
                        const float wl = sf[O_WLAST + h];
                        float pre = fmaf(yyv, wl, acc[i][j][2 * ci + cj]) + sf[O_B1 + h];
                        float g = (pre >= 0.0f) ? sf[O_W2 + h] : SLOPE * sf[O_W2 + h];
                        rp = fmaf(pre, g, rp);
                        jp = fmaf(g, wl, jp);
                        uint32_t bit = (pre >= 0.0f) ? (1u << (8 * (j & 3) + 2 * lc + cj)) : 0u;
                        if (j < 4) m0 |= bit; else m1 |= bit;
                    }
                }
                m0 |= __shfl_xor_sync(0xffffffffu, m0, 1);
                m0 |= __shfl_xor_sync(0xffffffffu, m0, 2);
                m1 |= __shfl_xor_sync(0xffffffffu, m1, 1);
                m1 |= __shfl_xor_sync(0xffffffffu, m1, 2);
                if (lc == 0) {
                    smemu[O_MASK + row * 4 + (hblk >> 5)]     = m0;
                    smemu[O_MASK + row * 4 + (hblk >> 5) + 1] = m1;
                }
                rp += __shfl_xor_sync(0xffffffffu, rp, 1);
                rp += __shfl_xor_sync(0xffffffffu, rp, 2);
                jp += __shfl_xor_sync(0xffffffffu, jp, 1);
                jp += __shfl_xor_sync(0xffffffffu, jp, 2);
                if (lc == 0) {
                    atomicAdd(&sf[O_RS + row], rp);
                    atomicAdd(&sf[O_JS + row], jp);
                }
            }
        }
    }
    __syncthreads();

    // residual + logdet outputs
    if (tid < 128) {
        const int n = tid;
        out[RES_OFF + ((size_t)(bb * TTt + t0 + n)) * Dd + d] = sf[O_RS + n] + __ldg(&b2[d]);
        float ls = logf(fabsf(sf[O_JS + n]));
        #pragma unroll
        for (int o = 16; o; o >>= 1) ls += __shfl_down_sync(0xffffffffu, ls, o);
        if (lane == 0) atomicAdd(&sf[O_RED], ls);
    }

    // ---------------- GEMM B: jac = SLOPE*S + RCOEF*((mask.*w2) @ W1)  (3xTF32) ---------
    const int nblk2 = (w & 3) * 32;
    const int kblk  = (w >> 2) * 32;

    uint32_t mA[2][4], mB[2][4];
    #pragma unroll
    for (int i = 0; i < 2; i++) {
        const int r1 = nblk2 + 16 * i + lr;
        #pragma unroll
        for (int q = 0; q < 4; q++) {
            mA[i][q] = smemu[O_MASK + r1 * 4 + q];
            mB[i][q] = smemu[O_MASK + (r1 + 8) * 4 + q];
        }
    }

    float acc2[2][4][4];
    #pragma unroll
    for (int i = 0; i < 2; i++)
        #pragma unroll
        for (int j = 0; j < 4; j++)
            #pragma unroll
            for (int q = 0; q < 4; q++) acc2[i][j][q] = 0.0f;

    #pragma unroll 4
    for (int s = 0; s < 16; s++) {
        const int bit0 = 8 * (s & 3) + lc;
        const int ws   = s >> 2;
        const uint32_t w2hA = smemu[O_W2H + 8 * s + lc];
        const uint32_t w2lA = smemu[O_W2L + 8 * s + lc];
        const uint32_t w2hB = smemu[O_W2H + 8 * s + lc + 4];
        const uint32_t w2lB = smemu[O_W2L + 8 * s + lc + 4];
        uint32_t ahg[2][4], alg[2][4];
        #pragma unroll
        for (int i = 0; i < 2; i++) {
            uint32_t bA0 = (mA[i][ws] >> bit0) & 1u;
            uint32_t bB0 = (mB[i][ws] >> bit0) & 1u;
            uint32_t bA4 = (mA[i][ws] >> (bit0 + 4)) & 1u;
            uint32_t bB4 = (mB[i][ws] >> (bit0 + 4)) & 1u;
            ahg[i][0] = bA0 ? w2hA : 0u;  alg[i][0] = bA0 ? w2lA : 0u;
            ahg[i][1] = bB0 ? w2hA : 0u;  alg[i][1] = bB0 ? w2lA : 0u;
            ahg[i][2] = bA4 ? w2hB : 0u;  alg[i][2] = bA4 ? w2lB : 0u;
            ahg[i][3] = bB4 ? w2hB : 0u;  alg[i][3] = bB4 ? w2lB : 0u;
        }
        #pragma unroll
        for (int j = 0; j < 4; j++) {
            const int kp = kblk + 8 * j + lr;
            const int r0 = (8 * s + lc) * W1S + kp;
            const int r1 = (8 * s + lc + 4) * W1S + kp;
            uint32_t bh0 = smemu[O_W1H + r0], bh1 = smemu[O_W1H + r1];
            uint32_t bl0 = smemu[O_W1L + r0], bl1 = smemu[O_W1L + r1];
            #pragma unroll
            for (int i = 0; i < 2; i++) {
                mma8(acc2[i][j], ahg[i], bh0, bh1);
                mma8(acc2[i][j], ahg[i], bl0, bl1);
                mma8(acc2[i][j], alg[i], bh0, bh1);
            }
        }
    }

    // write hist_jac: jac = SLOPE*S[k] + RCOEF*acc2
    #pragma unroll
    for (int i = 0; i < 2; i++) {
        #pragma unroll
        for (int ci = 0; ci < 2; ci++) {
            const int r = nblk2 + 16 * i + 8 * ci + lr;
            float* hb = out + HIST_OFF + ((size_t)d * NTOT + n0 + r) * 64;
            #pragma unroll
            for (int j = 0; j < 4; j++) {
                const int col = kblk + 8 * j + 2 * lc;
                const float s0 = sf[O_S + col];
                const float s1 = sf[O_S + col + 1];
                float2 v = make_float2(fmaf(RCOEF, acc2[i][j][2 * ci],     SLOPE * s0),
                                       fmaf(RCOEF, acc2[i][j][2 * ci + 1], SLOPE * s1));
                *(float2*)(hb + col) = v;
            }
        }
    }

    __syncthreads();
    if (tid == 0) atomicAdd(&out[SUM_OFF + bb], sf[O_RED]);
}

extern "C" void kernel_launch(void* const* d_in, const int* in_sizes, int n_in,
                              void* d_out, int out_size) {
    const float* x  = (const float*)d_in[0];
    const float* W1 = (const float*)d_in[1];
    const float* b1 = (const float*)d_in[2];
    const float* W2 = (const float*)d_in[3];
    const float* b2 = (const float*)d_in[4];
    float* out = (float*)d_out;

    cudaFuncSetAttribute(fused_mma, cudaFuncAttributeMaxDynamicSharedMemorySize, SMEM_BYTES);

    zero_sum_kernel<<<1, Bb>>>(out);
    fused_mma<<<dim3(Dd, NTILES), 256, SMEM_BYTES>>>(x, W1, b1, W2, b2, out);
}